// round 15
// baseline (speedup 1.0000x reference)
#include <cuda_runtime.h>
#include <math.h>

#define N_NODES 32000
#define N_EDGES 256000
#define N_GRAPHS 64
#define IN_DIM 64
#define TDIM 32
#define XTDIM 96          // IN_DIM + TDIM
#define D 128
#define HEADS 4
#define CH 32
#define ED 16
#define LAYERS 4
#define FFD 512

// per-layer permuted-weight block: qkvs(4*16384) + ff1(4*16384) + ff2(65536)
#define WP_LAYER 196608
#define WP_FF1_OFF 65536
#define WP_FF2_OFF 131072

// ---------------- scratch (static __device__, no allocation) ----------------
__device__ float g_h[N_NODES * D];
__device__ float g_xt[N_NODES * XTDIM];
__device__ float g_qkvs[N_NODES * 4 * D];   // [q | k | v | skip]
__device__ float g_att[N_NODES * D];
__device__ float g_ff1[N_NODES * FFD];
__device__ float g_y[N_NODES * D];
__device__ float g_Wp[LAYERS * WP_LAYER];   // permuted per-layer weights
__device__ float g_Wp_in[16 * 12 * 64];     // permuted Win (K=96)
__device__ int   g_deg[N_NODES];
__device__ int   g_fill[N_NODES];
__device__ int   g_rowptr[N_NODES + 1];
__device__ int   g_csr_src[N_EDGES];
__device__ int   g_csr_eid[N_EDGES];
__device__ int   g_tmax[N_GRAPHS];
__device__ int   g_cnt[N_GRAPHS];
__device__ float g_gsum[N_GRAPHS * D];
__device__ unsigned g_gmaxe[N_GRAPHS * D];

__device__ __forceinline__ unsigned fenc(float f) {
    unsigned u = __float_as_uint(f);
    return (u & 0x80000000u) ? ~u : (u | 0x80000000u);
}
__device__ __forceinline__ float fdec(unsigned u) {
    return (u & 0x80000000u) ? __uint_as_float(u ^ 0x80000000u) : __uint_as_float(~u);
}

__device__ __forceinline__ void mma_tf32(float* c, const unsigned* a, const unsigned* b) {
    asm volatile(
        "mma.sync.aligned.m16n8k8.row.col.f32.tf32.tf32.f32 "
        "{%0,%1,%2,%3}, {%4,%5,%6,%7}, {%8,%9}, {%0,%1,%2,%3};"
        : "+f"(c[0]), "+f"(c[1]), "+f"(c[2]), "+f"(c[3])
        : "r"(a[0]), "r"(a[1]), "r"(a[2]), "r"(a[3]), "r"(b[0]), "r"(b[1]));
}

// ---------------- weight permutation into HMMA fragment order ----------------
__global__ void permute_kernel(const float* __restrict__ W, float* __restrict__ dst,
                               int K, int N, int srcStride, int dstStride) {
    int layer = blockIdx.y;
    const float* Ws = W + (size_t)layer * srcStride;
    float* ds = dst + (size_t)layer * dstStride;
    int KS = K >> 3;
    int total = K * N;
    for (int idx = blockIdx.x * blockDim.x + threadIdx.x; idx < total; idx += gridDim.x * blockDim.x) {
        int k = idx / N, n = idx % N;
        int tile = n >> 7, nn = n & 127;
        int gnf = nn >> 3, ks = k >> 3;
        int ln = ((nn & 7) << 2) | (k & 3);
        int rg = (k >> 2) & 1;
        ds[(size_t)tile * 16 * KS * 64 + ((size_t)(gnf * KS + ks)) * 64 + ln * 2 + rg] = Ws[idx];
    }
}

// ---------------- prep ----------------
__global__ void prep_kernel() {
    int idx = blockIdx.x * blockDim.x + threadIdx.x;
    if (idx < N_NODES) { g_deg[idx] = 0; g_fill[idx] = 0; }
    if (idx < N_GRAPHS * D) { g_gsum[idx] = 0.f; g_gmaxe[idx] = fenc(-1e30f); }
    if (idx < N_GRAPHS) { g_cnt[idx] = 0; g_tmax[idx] = -1; }
}

// ---------------- xt = [x, time_enc(t)] ----------------
__global__ void build_xt_kernel(const float* __restrict__ x, const int* __restrict__ t) {
    int idx = blockIdx.x * blockDim.x + threadIdx.x;
    if (idx >= N_NODES * XTDIM) return;
    int n = idx / XTDIM, f = idx % XTDIM;
    float v;
    if (f < IN_DIM) {
        v = x[n * IN_DIM + f];
    } else {
        int j = f - IN_DIM;
        int jj = (j < 16) ? j : j - 16;
        float fac = __expf((float)jj * -0.61402269146507887f);
        float ang = (float)t[n] * fac;
        v = (j < 16) ? sinf(ang) : cosf(ang);
    }
    g_xt[idx] = v;
}

// ---------------- CSR build ----------------
__global__ void deg_kernel(const int* __restrict__ ei) {
    int j = blockIdx.x * blockDim.x + threadIdx.x;
    if (j < N_EDGES) atomicAdd(&g_deg[ei[N_EDGES + j]], 1);
}

__global__ void scan_kernel() {
    __shared__ int s[1024];
    __shared__ int carry;
    int tid = threadIdx.x;
    if (tid == 0) { carry = 0; g_rowptr[0] = 0; }
    __syncthreads();
    for (int base = 0; base < N_NODES; base += 1024) {
        int i = base + tid;
        int v = (i < N_NODES) ? g_deg[i] : 0;
        s[tid] = v;
        __syncthreads();
        for (int off = 1; off < 1024; off <<= 1) {
            int t2 = (tid >= off) ? s[tid - off] : 0;
            __syncthreads();
            s[tid] += t2;
            __syncthreads();
        }
        if (i < N_NODES) g_rowptr[i + 1] = s[tid] + carry;
        __syncthreads();
        if (tid == 0) carry += s[1023];
        __syncthreads();
    }
}

__global__ void fill_kernel(const int* __restrict__ ei) {
    int j = blockIdx.x * blockDim.x + threadIdx.x;
    if (j >= N_EDGES) return;
    int d = ei[N_EDGES + j];
    int p = atomicAdd(&g_fill[d], 1);
    int idx = g_rowptr[d] + p;
    g_csr_src[idx] = ei[j];
    g_csr_eid[idx] = j;
}

// =====================================================================
// tf32 GEMM v5b: 128x128 C-tile. A tile global->smem via cp.async.
// B direct from pre-permuted global with depth-2 rolling prefetch.
// =====================================================================
#define ASTRIDE 36
template <int ACT>
__global__ void __launch_bounds__(256, 2)
tgemm(const float* __restrict__ A, const float* __restrict__ Bp,
      const float* __restrict__ g0, const float* __restrict__ g1,
      const float* __restrict__ g2, const float* __restrict__ g3,
      float* __restrict__ C, int K, int blksPerMat, int ldc) {
    __shared__ __align__(16) float As[2][128 * ASTRIDE];

    const int tid = threadIdx.x;
    const int warp = tid >> 5, lane = tid & 31;
    const int wm = warp >> 2, wn = warp & 3;
    const int KS = K >> 3;
    const int ksLast = KS - 1;
    const int bx = blockIdx.x;
    const int mat = bx / blksPerMat;
    const int colInMat = (bx % blksPerMat) * 128;
    const int colC = bx * 128;
    const int rowBase = blockIdx.y * 128;
    const float* bias = (mat == 0) ? g0 : (mat == 1) ? g1 : (mat == 2) ? g2 : g3;
    const float* Bt = Bp + (size_t)bx * 16 * KS * 64;

    const float* Bw0 = Bt + ((size_t)(wn * 4 + 0) * KS) * 64 + lane * 2;
    const float* Bw1 = Bt + ((size_t)(wn * 4 + 1) * KS) * 64 + lane * 2;
    const float* Bw2 = Bt + ((size_t)(wn * 4 + 2) * KS) * 64 + lane * 2;
    const float* Bw3 = Bt + ((size_t)(wn * 4 + 3) * KS) * 64 + lane * 2;

    float c[4][4][4];
    #pragma unroll
    for (int f = 0; f < 4; f++)
        #pragma unroll
        for (int n = 0; n < 4; n++)
            #pragma unroll
            for (int j = 0; j < 4; j++) c[f][n][j] = 0.f;

    const int arow = tid >> 1;
    const int acg0 = (tid & 1) * 4;
    unsigned sb0 = (unsigned)__cvta_generic_to_shared(&As[0][arow * ASTRIDE]);
    unsigned sb1 = (unsigned)__cvta_generic_to_shared(&As[1][arow * ASTRIDE]);
    const float* agp = &A[(size_t)(rowBase + arow) * K];

    auto cpA = [&](int k0, int buf) {
        unsigned sb = buf ? sb1 : sb0;
        #pragma unroll
        for (int i = 0; i < 4; i++) {
            int cg = acg0 + i;
            unsigned saddr = sb + (unsigned)(cg * 16);
            const float* gp = agp + k0 + cg * 4;
            asm volatile("cp.async.ca.shared.global [%0], [%1], 16;"
                         :: "r"(saddr), "l"(gp));
        }
        asm volatile("cp.async.commit_group;" ::: "memory");
    };

    cpA(0, 0);
    float2 bcur[4], bn1[4];
    bcur[0] = *(const float2*)&Bw0[0];
    bcur[1] = *(const float2*)&Bw1[0];
    bcur[2] = *(const float2*)&Bw2[0];
    bcur[3] = *(const float2*)&Bw3[0];
    {
        int k1 = (1 > ksLast) ? ksLast : 1;
        bn1[0] = *(const float2*)&Bw0[(size_t)k1 * 64];
        bn1[1] = *(const float2*)&Bw1[(size_t)k1 * 64];
        bn1[2] = *(const float2*)&Bw2[(size_t)k1 * 64];
        bn1[3] = *(const float2*)&Bw3[(size_t)k1 * 64];
    }
    asm volatile("cp.async.wait_group 0;" ::: "memory");
    __syncthreads();

    int buf = 0;
    for (int kt = 0;; kt += 32) {
        bool hasNext = (kt + 32) < K;
        if (hasNext) cpA(kt + 32, buf ^ 1);
        int ks0 = kt >> 3;
        #pragma unroll
        for (int s = 0; s < 4; s++) {
            int ksn = ks0 + s + 2;
            if (ksn > ksLast) ksn = ksLast;
            float2 bn2[4];
            bn2[0] = *(const float2*)&Bw0[(size_t)ksn * 64];
            bn2[1] = *(const float2*)&Bw1[(size_t)ksn * 64];
            bn2[2] = *(const float2*)&Bw2[(size_t)ksn * 64];
            bn2[3] = *(const float2*)&Bw3[(size_t)ksn * 64];
            unsigned af[4][4];
            #pragma unroll
            for (int f = 0; f < 4; f++) {
                int base = (wm * 64 + f * 16 + (lane >> 2)) * ASTRIDE + s * 8 + (lane & 3);
                af[f][0] = __float_as_uint(As[buf][base]);
                af[f][1] = __float_as_uint(As[buf][base + 8 * ASTRIDE]);
                af[f][2] = __float_as_uint(As[buf][base + 4]);
                af[f][3] = __float_as_uint(As[buf][base + 8 * ASTRIDE + 4]);
            }
            #pragma unroll
            for (int f = 0; f < 4; f++)
                #pragma unroll
                for (int n = 0; n < 4; n++) {
                    unsigned bf[2] = { __float_as_uint(bcur[n].x), __float_as_uint(bcur[n].y) };
                    mma_tf32(c[f][n], af[f], bf);
                }
            #pragma unroll
            for (int n = 0; n < 4; n++) { bcur[n] = bn1[n]; bn1[n] = bn2[n]; }
        }
        if (!hasNext) break;
        asm volatile("cp.async.wait_group 0;" ::: "memory");
        __syncthreads();
        buf ^= 1;
    }

    #pragma unroll
    for (int f = 0; f < 4; f++) {
        int r0 = rowBase + wm * 64 + f * 16 + (lane >> 2);
        #pragma unroll
        for (int n = 0; n < 4; n++) {
            int cb = wn * 32 + n * 8 + (lane & 3) * 2;
            float b0 = bias[colInMat + cb], b1 = bias[colInMat + cb + 1];
            float v0 = c[f][n][0] + b0, v1 = c[f][n][1] + b1;
            float v2 = c[f][n][2] + b0, v3 = c[f][n][3] + b1;
            if (ACT == 1) {
                v0 = fmaxf(v0, 0.f); v1 = fmaxf(v1, 0.f);
                v2 = fmaxf(v2, 0.f); v3 = fmaxf(v3, 0.f);
            }
            *(float2*)&C[(size_t)r0 * ldc + colC + cb] = make_float2(v0, v1);
            *(float2*)&C[(size_t)(r0 + 8) * ldc + colC + cb] = make_float2(v2, v3);
        }
    }
}

// ---------------- fused attention (with in-block qe): warp per (node, head) ----------------
// unrolled-by-2 edge loop; qe computed in smem from staged q rows.
__global__ void __launch_bounds__(512, 2)
attn_kernel(const float* __restrict__ ea,
            const float* __restrict__ We, const float* __restrict__ be) {
    __shared__ float sWe[ED * D];
    __shared__ float sbe[D];
    __shared__ float sq[4][D];
    __shared__ float sqe[4][64];
    int tid = threadIdx.x;  // 512 = 4 nodes x 4 heads
    int nodeBase = blockIdx.x * 4;
    for (int i = tid; i < ED * D; i += 512) sWe[i] = We[i];
    if (tid < D) sbe[tid] = be[tid];
    {
        int nn = tid >> 7, c = tid & 127;   // 512 threads cover 4x128
        sq[nn][c] = g_qkvs[(size_t)(nodeBase + nn) * 512 + c];
    }
    __syncthreads();
    // qe[nl][h*16+f] = scale * sum_c q[nl][h*32+c] * We[f*D + h*32+c]
    if (tid < 256) {
        int nl = tid >> 6;
        int hf = tid & 63;
        int h = hf >> 4, f = hf & 15;
        float acc = 0.f;
        #pragma unroll
        for (int c = 0; c < 32; c++)
            acc += sq[nl][h * 32 + c] * sWe[f * D + h * 32 + c];
        sqe[nl][hf] = acc * 0.17677669529663687f;
    }
    __syncthreads();

    int warp = tid >> 5, lane = tid & 31;
    int nl = warp >> 2;
    int node = nodeBase + nl;
    int h = warp & 3;
    int ch = (h << 5) | lane;
    float q = sq[nl][ch] * 0.17677669529663687f;
    float qe = (lane < 16) ? sqe[nl][h * 16 + lane] : 0.f;
    int e0 = g_rowptr[node], e1 = g_rowptr[node + 1];
    float m = -INFINITY, den = 0.f, accv = 0.f, wea = 0.f;
    int e = e0;
    for (; e + 1 < e1; e += 2) {
        int s0 = g_csr_src[e],     id0 = g_csr_eid[e];
        int s1 = g_csr_src[e + 1], id1 = g_csr_eid[e + 1];
        const float* r0 = g_qkvs + (size_t)s0 * 512;
        const float* r1 = g_qkvs + (size_t)s1 * 512;
        float kk0 = r0[D + ch];
        float kk1 = r1[D + ch];
        float vv0 = r0[2 * D + ch];
        float vv1 = r1[2 * D + ch];
        float ea0 = (lane < 16) ? ea[(size_t)id0 * ED + lane] : 0.f;
        float ea1 = (lane < 16) ? ea[(size_t)id1 * ED + lane] : 0.f;
        float p0 = q * kk0 + qe * ea0;
        float p1 = q * kk1 + qe * ea1;
        #pragma unroll
        for (int o = 16; o; o >>= 1) {
            p0 += __shfl_xor_sync(0xffffffffu, p0, o);
            p1 += __shfl_xor_sync(0xffffffffu, p1, o);
        }
        float mn = fmaxf(m, fmaxf(p0, p1));
        float sc = __expf(m - mn);
        float w0 = __expf(p0 - mn);
        float w1 = __expf(p1 - mn);
        den  = den  * sc + w0 + w1;
        accv = accv * sc + w0 * vv0 + w1 * vv1;
        wea  = wea  * sc + w0 * ea0 + w1 * ea1;
        m = mn;
    }
    if (e < e1) {
        int s0 = g_csr_src[e], id0 = g_csr_eid[e];
        const float* r0 = g_qkvs + (size_t)s0 * 512;
        float kk0 = r0[D + ch];
        float vv0 = r0[2 * D + ch];
        float ea0 = (lane < 16) ? ea[(size_t)id0 * ED + lane] : 0.f;
        float p0 = q * kk0 + qe * ea0;
        #pragma unroll
        for (int o = 16; o; o >>= 1) p0 += __shfl_xor_sync(0xffffffffu, p0, o);
        float mn = fmaxf(m, p0);
        float sc = __expf(m - mn);
        float w0 = __expf(p0 - mn);
        den  = den  * sc + w0;
        accv = accv * sc + w0 * vv0;
        wea  = wea  * sc + w0 * ea0;
        m = mn;
    }
    float out = 0.f;
    if (e1 > e0) {
        float inv = 1.f / den;
        float wn = wea * inv;
        out = accv * inv + sbe[ch];
        #pragma unroll
        for (int f = 0; f < 16; f++) {
            float wf = __shfl_sync(0xffffffffu, wn, f);
            out += wf * sWe[f * D + ch];
        }
    }
    g_att[(size_t)node * D + ch] = out;
}

// ---------------- beta-gated skip + residual + LN1 (warp per node) ----------------
__global__ void betaln1_kernel(const float* __restrict__ Wb,
                               const float* __restrict__ g1, const float* __restrict__ b1) {
    int warp = threadIdx.x >> 5;
    int n = blockIdx.x * 8 + warp;
    int lane = threadIdx.x & 31;
    float o[4], xr[4];
    float bdot = 0.f;
    #pragma unroll
    for (int i = 0; i < 4; i++) {
        int c = lane + 32 * i;
        o[i] = g_att[(size_t)n * D + c];
        xr[i] = g_qkvs[(size_t)n * 512 + 384 + c];
        bdot += o[i] * Wb[c] + xr[i] * Wb[D + c] + (o[i] - xr[i]) * Wb[2 * D + c];
    }
    #pragma unroll
    for (int off = 16; off; off >>= 1) bdot += __shfl_xor_sync(0xffffffffu, bdot, off);
    float beta = 1.f / (1.f + __expf(-bdot));
    float hn[4];
    float s = 0.f;
    #pragma unroll
    for (int i = 0; i < 4; i++) {
        int c = lane + 32 * i;
        hn[i] = g_h[(size_t)n * D + c] + beta * xr[i] + (1.f - beta) * o[i];
        s += hn[i];
    }
    #pragma unroll
    for (int off = 16; off; off >>= 1) s += __shfl_xor_sync(0xffffffffu, s, off);
    float mean = s * (1.f / D);
    float vs = 0.f;
    #pragma unroll
    for (int i = 0; i < 4; i++) { float dd = hn[i] - mean; vs += dd * dd; }
    #pragma unroll
    for (int off = 16; off; off >>= 1) vs += __shfl_xor_sync(0xffffffffu, vs, off);
    float inv = rsqrtf(vs * (1.f / D) + 1e-5f);
    #pragma unroll
    for (int i = 0; i < 4; i++) {
        int c = lane + 32 * i;
        g_h[(size_t)n * D + c] = (hn[i] - mean) * inv * g1[c] + b1[c];
    }
}

// ---------------- residual + LN2 (warp per node) ----------------
__global__ void ln2_kernel(const float* __restrict__ g2, const float* __restrict__ b2) {
    int warp = threadIdx.x >> 5;
    int n = blockIdx.x * 8 + warp;
    int lane = threadIdx.x & 31;
    float hn[4];
    float s = 0.f;
    #pragma unroll
    for (int i = 0; i < 4; i++) {
        int c = lane + 32 * i;
        hn[i] = g_h[(size_t)n * D + c] + g_y[(size_t)n * D + c];
        s += hn[i];
    }
    #pragma unroll
    for (int off = 16; off; off >>= 1) s += __shfl_xor_sync(0xffffffffu, s, off);
    float mean = s * (1.f / D);
    float vs = 0.f;
    #pragma unroll
    for (int i = 0; i < 4; i++) { float dd = hn[i] - mean; vs += dd * dd; }
    #pragma unroll
    for (int off = 16; off; off >>= 1) vs += __shfl_xor_sync(0xffffffffu, vs, off);
    float inv = rsqrtf(vs * (1.f / D) + 1e-5f);
    #pragma unroll
    for (int i = 0; i < 4; i++) {
        int c = lane + 32 * i;
        g_h[(size_t)n * D + c] = (hn[i] - mean) * inv * g2[c] + b2[c];
    }
}

// ---------------- readout ----------------
__global__ void tmax_kernel(const int* __restrict__ t, const int* __restrict__ batch) {
    int n = blockIdx.x * blockDim.x + threadIdx.x;
    if (n < N_NODES) atomicMax(&g_tmax[batch[n]], t[n]);
}

__global__ void maskacc_kernel(const int* __restrict__ t, const int* __restrict__ batch) {
    int idx = blockIdx.x * blockDim.x + threadIdx.x;
    if (idx >= N_NODES * D) return;
    int n = idx >> 7, c = idx & 127;
    int b = batch[n];
    if (t[n] == g_tmax[b]) {
        float hv = g_h[idx];
        atomicAdd(&g_gsum[b * D + c], hv);
        atomicMax(&g_gmaxe[b * D + c], fenc(hv));
        if (c == 0) atomicAdd(&g_cnt[b], 1);
    }
}

__global__ void mlp_kernel(const float* __restrict__ Wh1, const float* __restrict__ bh1,
                           const float* __restrict__ Wh2, const float* __restrict__ bh2,
                           float* __restrict__ out) {
    __shared__ float sg[2 * D];
    __shared__ float sa[D];
    int g = blockIdx.x;
    int c = threadIdx.x;  // 128
    float cnt = fmaxf((float)g_cnt[g], 1.f);
    sg[c] = g_gsum[g * D + c] / cnt;
    sg[D + c] = fdec(g_gmaxe[g * D + c]);
    __syncthreads();
    float a = bh1[c];
    #pragma unroll 8
    for (int j = 0; j < 2 * D; j++) a += sg[j] * Wh1[j * D + c];
    sa[c] = fmaxf(a, 0.f);
    __syncthreads();
    if (c < 2) {
        float s2 = bh2[c];
        for (int j = 0; j < D; j++) s2 += sa[j] * Wh2[j * 2 + c];
        out[g * 2 + c] = s2;
    }
}

// ---------------- host orchestration ----------------
extern "C" void kernel_launch(void* const* d_in, const int* in_sizes, int n_in,
                              void* d_out, int out_size) {
    const float* x     = (const float*)d_in[0];
    const int*   t     = (const int*)d_in[1];
    const int*   ei    = (const int*)d_in[2];
    const float* ea    = (const float*)d_in[3];
    const int*   batch = (const int*)d_in[4];
    const float* Win   = (const float*)d_in[5];
    const float* b_in  = (const float*)d_in[6];
    const float* Wq    = (const float*)d_in[7];
    const float* bq    = (const float*)d_in[8];
    const float* Wk    = (const float*)d_in[9];
    const float* bk    = (const float*)d_in[10];
    const float* Wv    = (const float*)d_in[11];
    const float* bv    = (const float*)d_in[12];
    const float* We    = (const float*)d_in[13];
    const float* be    = (const float*)d_in[14];
    const float* Wskip = (const float*)d_in[15];
    const float* bskip = (const float*)d_in[16];
    const float* Wbeta = (const float*)d_in[17];
    const float* ln1_g = (const float*)d_in[18];
    const float* ln1_b = (const float*)d_in[19];
    const float* Wff1  = (const float*)d_in[20];
    const float* bff1  = (const float*)d_in[21];
    const float* Wff2  = (const float*)d_in[22];
    const float* bff2  = (const float*)d_in[23];
    const float* ln2_g = (const float*)d_in[24];
    const float* ln2_b = (const float*)d_in[25];
    const float* Wh1   = (const float*)d_in[26];
    const float* bh1   = (const float*)d_in[27];
    const float* Wh2   = (const float*)d_in[28];
    const float* bh2   = (const float*)d_in[29];
    float* out = (float*)d_out;

    float *p_h, *p_xt, *p_qkvs, *p_ff1, *p_y, *p_Wp, *p_Wp_in;
    cudaGetSymbolAddress((void**)&p_h, g_h);
    cudaGetSymbolAddress((void**)&p_xt, g_xt);
    cudaGetSymbolAddress((void**)&p_qkvs, g_qkvs);
    cudaGetSymbolAddress((void**)&p_ff1, g_ff1);
    cudaGetSymbolAddress((void**)&p_y, g_y);
    cudaGetSymbolAddress((void**)&p_Wp, g_Wp);
    cudaGetSymbolAddress((void**)&p_Wp_in, g_Wp_in);

    // order keeps the input tgemm at launch index 3 (ncu capture slot)
    prep_kernel<<<125, 256>>>();                                           // 0
    permute_kernel<<<dim3(48, 1), 256>>>(Win, p_Wp_in, XTDIM, D, 0, 0);    // 1
    build_xt_kernel<<<(N_NODES * XTDIM + 255) / 256, 256>>>(x, t);         // 2
    tgemm<1><<<dim3(1, 250), 256>>>(p_xt, p_Wp_in,                          // 3
                                    b_in, b_in, b_in, b_in,
                                    p_h, XTDIM, 1, D);
    deg_kernel<<<1000, 256>>>(ei);
    scan_kernel<<<1, 1024>>>();
    fill_kernel<<<1000, 256>>>(ei);
    permute_kernel<<<dim3(64, LAYERS), 256>>>(Wq,    p_Wp + 0 * 16384,  D, D,   D * D,    WP_LAYER);
    permute_kernel<<<dim3(64, LAYERS), 256>>>(Wk,    p_Wp + 1 * 16384,  D, D,   D * D,    WP_LAYER);
    permute_kernel<<<dim3(64, LAYERS), 256>>>(Wv,    p_Wp + 2 * 16384,  D, D,   D * D,    WP_LAYER);
    permute_kernel<<<dim3(64, LAYERS), 256>>>(Wskip, p_Wp + 3 * 16384,  D, D,   D * D,    WP_LAYER);
    permute_kernel<<<dim3(256, LAYERS), 256>>>(Wff1, p_Wp + WP_FF1_OFF, D, FFD, D * FFD,  WP_LAYER);
    permute_kernel<<<dim3(256, LAYERS), 256>>>(Wff2, p_Wp + WP_FF2_OFF, FFD, D, FFD * D,  WP_LAYER);

    for (int i = 0; i < LAYERS; i++) {
        const float* Wei = We + (size_t)i * ED * D;
        float* WpL = p_Wp + (size_t)i * WP_LAYER;
        tgemm<0><<<dim3(4, 250), 256>>>(p_h, WpL,
                                        bq + i * D, bk + i * D, bv + i * D, bskip + i * D,
                                        p_qkvs, D, 1, 512);
        attn_kernel<<<N_NODES / 4, 512>>>(ea, Wei, be + i * D);
        betaln1_kernel<<<N_NODES / 8, 256>>>(Wbeta + (size_t)i * 3 * D, ln1_g + i * D, ln1_b + i * D);

        tgemm<1><<<dim3(4, 250), 256>>>(p_h, WpL + WP_FF1_OFF,
                                        bff1 + i * FFD, nullptr, nullptr, nullptr,
                                        p_ff1, D, 4, FFD);
        tgemm<0><<<dim3(1, 250), 256>>>(p_ff1, WpL + WP_FF2_OFF,
                                        bff2 + i * D, nullptr, nullptr, nullptr,
                                        p_y, FFD, 1, D);
        ln2_kernel<<<N_NODES / 8, 256>>>(ln2_g + i * D, ln2_b + i * D);
    }

    tmax_kernel<<<125, 256>>>(t, batch);
    maskacc_kernel<<<(N_NODES * D + 255) / 256, 256>>>(t, batch);
    mlp_kernel<<<N_GRAPHS, 128>>>(Wh1, bh1, Wh2, bh2, out);
    (void)in_sizes; (void)n_in; (void)out_size;
}

// round 16
// speedup vs baseline: 1.6237x; 1.6237x over previous
#include <cuda_runtime.h>
#include <math.h>

#define N_NODES 32000
#define N_EDGES 256000
#define N_GRAPHS 64
#define IN_DIM 64
#define TDIM 32
#define XTDIM 96          // IN_DIM + TDIM
#define D 128
#define HEADS 4
#define CH 32
#define ED 16
#define LAYERS 4
#define FFD 512

// per-layer permuted-weight block: qkvs(4*16384) + ff1(4*16384) + ff2(65536)
#define WP_LAYER 196608
#define WP_FF1_OFF 65536
#define WP_FF2_OFF 131072

#define SCAN_BLOCKS 125   // 125 * 256 = 32000

// ---------------- scratch (static __device__, no allocation) ----------------
__device__ float g_h[N_NODES * D];
__device__ float g_xt[N_NODES * XTDIM];
__device__ float g_qkvs[N_NODES * 4 * D];   // [q | k | v | skip]
__device__ float g_att[N_NODES * D];
__device__ float g_ff1[N_NODES * FFD];
__device__ float g_y[N_NODES * D];
__device__ float g_qe[N_NODES * 64];        // per-node We^T q, pre-scaled
__device__ float g_Wp[LAYERS * WP_LAYER];   // permuted per-layer weights
__device__ float g_Wp_in[16 * 12 * 64];     // permuted Win (K=96)
__device__ int   g_deg[N_NODES];
__device__ int   g_fill[N_NODES];
__device__ int   g_rowptr[N_NODES + 1];
__device__ int   g_blocksum[SCAN_BLOCKS];
__device__ int   g_blockoff[SCAN_BLOCKS];
__device__ int   g_csr_src[N_EDGES];
__device__ int   g_csr_eid[N_EDGES];
__device__ int   g_tmax[N_GRAPHS];
__device__ int   g_cnt[N_GRAPHS];
__device__ float g_gsum[N_GRAPHS * D];
__device__ unsigned g_gmaxe[N_GRAPHS * D];

__device__ __forceinline__ unsigned fenc(float f) {
    unsigned u = __float_as_uint(f);
    return (u & 0x80000000u) ? ~u : (u | 0x80000000u);
}
__device__ __forceinline__ float fdec(unsigned u) {
    return (u & 0x80000000u) ? __uint_as_float(u ^ 0x80000000u) : __uint_as_float(~u);
}

__device__ __forceinline__ void mma_tf32(float* c, const unsigned* a, const unsigned* b) {
    asm volatile(
        "mma.sync.aligned.m16n8k8.row.col.f32.tf32.tf32.f32 "
        "{%0,%1,%2,%3}, {%4,%5,%6,%7}, {%8,%9}, {%0,%1,%2,%3};"
        : "+f"(c[0]), "+f"(c[1]), "+f"(c[2]), "+f"(c[3])
        : "r"(a[0]), "r"(a[1]), "r"(a[2]), "r"(a[3]), "r"(b[0]), "r"(b[1]));
}

// ---------------- weight permutation into HMMA fragment order ----------------
__global__ void permute_kernel(const float* __restrict__ W, float* __restrict__ dst,
                               int K, int N, int srcStride, int dstStride) {
    int layer = blockIdx.y;
    const float* Ws = W + (size_t)layer * srcStride;
    float* ds = dst + (size_t)layer * dstStride;
    int KS = K >> 3;
    int total = K * N;
    for (int idx = blockIdx.x * blockDim.x + threadIdx.x; idx < total; idx += gridDim.x * blockDim.x) {
        int k = idx / N, n = idx % N;
        int tile = n >> 7, nn = n & 127;
        int gnf = nn >> 3, ks = k >> 3;
        int ln = ((nn & 7) << 2) | (k & 3);
        int rg = (k >> 2) & 1;
        ds[(size_t)tile * 16 * KS * 64 + ((size_t)(gnf * KS + ks)) * 64 + ln * 2 + rg] = Ws[idx];
    }
}

// ---------------- prep ----------------
__global__ void prep_kernel() {
    int idx = blockIdx.x * blockDim.x + threadIdx.x;
    if (idx < N_NODES) { g_deg[idx] = 0; g_fill[idx] = 0; }
    if (idx < N_GRAPHS * D) { g_gsum[idx] = 0.f; g_gmaxe[idx] = fenc(-1e30f); }
    if (idx < N_GRAPHS) { g_cnt[idx] = 0; g_tmax[idx] = -1; }
}

// ---------------- xt = [x, time_enc(t)] ----------------
__global__ void build_xt_kernel(const float* __restrict__ x, const int* __restrict__ t) {
    int idx = blockIdx.x * blockDim.x + threadIdx.x;
    if (idx >= N_NODES * XTDIM) return;
    int n = idx / XTDIM, f = idx % XTDIM;
    float v;
    if (f < IN_DIM) {
        v = x[n * IN_DIM + f];
    } else {
        int j = f - IN_DIM;
        int jj = (j < 16) ? j : j - 16;
        float fac = __expf((float)jj * -0.61402269146507887f);
        float ang = (float)t[n] * fac;
        v = (j < 16) ? sinf(ang) : cosf(ang);
    }
    g_xt[idx] = v;
}

// ---------------- CSR build ----------------
__global__ void deg_kernel(const int* __restrict__ ei) {
    int j = blockIdx.x * blockDim.x + threadIdx.x;
    if (j < N_EDGES) atomicAdd(&g_deg[ei[N_EDGES + j]], 1);
}

// segmented scan, phase A: block-local inclusive scan of 256 entries
__global__ void scanA_kernel() {
    __shared__ int s[256];
    int tid = threadIdx.x;
    int i = blockIdx.x * 256 + tid;
    int v = g_deg[i];
    s[tid] = v;
    __syncthreads();
    #pragma unroll
    for (int off = 1; off < 256; off <<= 1) {
        int t2 = (tid >= off) ? s[tid - off] : 0;
        __syncthreads();
        s[tid] += t2;
        __syncthreads();
    }
    g_rowptr[i + 1] = s[tid];
    if (tid == 255) g_blocksum[blockIdx.x] = s[255];
}

// phase B: exclusive scan of block sums (1 block, 128 threads)
__global__ void scanB_kernel() {
    __shared__ int s[SCAN_BLOCKS];
    int tid = threadIdx.x;
    for (int i = tid; i < SCAN_BLOCKS; i += 128) s[i] = g_blocksum[i];
    __syncthreads();
    if (tid == 0) {
        int acc = 0;
        for (int i = 0; i < SCAN_BLOCKS; i++) {
            int t2 = s[i];
            s[i] = acc;
            acc += t2;
        }
    }
    __syncthreads();
    for (int i = tid; i < SCAN_BLOCKS; i += 128) g_blockoff[i] = s[i];
}

// phase C: add block offsets
__global__ void scanC_kernel() {
    int tid = threadIdx.x;
    int i = blockIdx.x * 256 + tid;
    g_rowptr[i + 1] += g_blockoff[blockIdx.x];
    if (i == 0) g_rowptr[0] = 0;
}

__global__ void fill_kernel(const int* __restrict__ ei) {
    int j = blockIdx.x * blockDim.x + threadIdx.x;
    if (j >= N_EDGES) return;
    int d = ei[N_EDGES + j];
    int p = atomicAdd(&g_fill[d], 1);
    int idx = g_rowptr[d] + p;
    g_csr_src[idx] = ei[j];
    g_csr_eid[idx] = j;
}

// =====================================================================
// tf32 GEMM v5b: 128x128 C-tile. A tile global->smem via cp.async.
// B direct from pre-permuted global with depth-2 rolling prefetch.
// =====================================================================
#define ASTRIDE 36
template <int ACT>
__global__ void __launch_bounds__(256, 2)
tgemm(const float* __restrict__ A, const float* __restrict__ Bp,
      const float* __restrict__ g0, const float* __restrict__ g1,
      const float* __restrict__ g2, const float* __restrict__ g3,
      float* __restrict__ C, int K, int blksPerMat, int ldc) {
    __shared__ __align__(16) float As[2][128 * ASTRIDE];

    const int tid = threadIdx.x;
    const int warp = tid >> 5, lane = tid & 31;
    const int wm = warp >> 2, wn = warp & 3;
    const int KS = K >> 3;
    const int ksLast = KS - 1;
    const int bx = blockIdx.x;
    const int mat = bx / blksPerMat;
    const int colInMat = (bx % blksPerMat) * 128;
    const int colC = bx * 128;
    const int rowBase = blockIdx.y * 128;
    const float* bias = (mat == 0) ? g0 : (mat == 1) ? g1 : (mat == 2) ? g2 : g3;
    const float* Bt = Bp + (size_t)bx * 16 * KS * 64;

    const float* Bw0 = Bt + ((size_t)(wn * 4 + 0) * KS) * 64 + lane * 2;
    const float* Bw1 = Bt + ((size_t)(wn * 4 + 1) * KS) * 64 + lane * 2;
    const float* Bw2 = Bt + ((size_t)(wn * 4 + 2) * KS) * 64 + lane * 2;
    const float* Bw3 = Bt + ((size_t)(wn * 4 + 3) * KS) * 64 + lane * 2;

    float c[4][4][4];
    #pragma unroll
    for (int f = 0; f < 4; f++)
        #pragma unroll
        for (int n = 0; n < 4; n++)
            #pragma unroll
            for (int j = 0; j < 4; j++) c[f][n][j] = 0.f;

    const int arow = tid >> 1;
    const int acg0 = (tid & 1) * 4;
    unsigned sb0 = (unsigned)__cvta_generic_to_shared(&As[0][arow * ASTRIDE]);
    unsigned sb1 = (unsigned)__cvta_generic_to_shared(&As[1][arow * ASTRIDE]);
    const float* agp = &A[(size_t)(rowBase + arow) * K];

    auto cpA = [&](int k0, int buf) {
        unsigned sb = buf ? sb1 : sb0;
        #pragma unroll
        for (int i = 0; i < 4; i++) {
            int cg = acg0 + i;
            unsigned saddr = sb + (unsigned)(cg * 16);
            const float* gp = agp + k0 + cg * 4;
            asm volatile("cp.async.ca.shared.global [%0], [%1], 16;"
                         :: "r"(saddr), "l"(gp));
        }
        asm volatile("cp.async.commit_group;" ::: "memory");
    };

    cpA(0, 0);
    float2 bcur[4], bn1[4];
    bcur[0] = *(const float2*)&Bw0[0];
    bcur[1] = *(const float2*)&Bw1[0];
    bcur[2] = *(const float2*)&Bw2[0];
    bcur[3] = *(const float2*)&Bw3[0];
    {
        int k1 = (1 > ksLast) ? ksLast : 1;
        bn1[0] = *(const float2*)&Bw0[(size_t)k1 * 64];
        bn1[1] = *(const float2*)&Bw1[(size_t)k1 * 64];
        bn1[2] = *(const float2*)&Bw2[(size_t)k1 * 64];
        bn1[3] = *(const float2*)&Bw3[(size_t)k1 * 64];
    }
    asm volatile("cp.async.wait_group 0;" ::: "memory");
    __syncthreads();

    int buf = 0;
    for (int kt = 0;; kt += 32) {
        bool hasNext = (kt + 32) < K;
        if (hasNext) cpA(kt + 32, buf ^ 1);
        int ks0 = kt >> 3;
        #pragma unroll
        for (int s = 0; s < 4; s++) {
            int ksn = ks0 + s + 2;
            if (ksn > ksLast) ksn = ksLast;
            float2 bn2[4];
            bn2[0] = *(const float2*)&Bw0[(size_t)ksn * 64];
            bn2[1] = *(const float2*)&Bw1[(size_t)ksn * 64];
            bn2[2] = *(const float2*)&Bw2[(size_t)ksn * 64];
            bn2[3] = *(const float2*)&Bw3[(size_t)ksn * 64];
            unsigned af[4][4];
            #pragma unroll
            for (int f = 0; f < 4; f++) {
                int base = (wm * 64 + f * 16 + (lane >> 2)) * ASTRIDE + s * 8 + (lane & 3);
                af[f][0] = __float_as_uint(As[buf][base]);
                af[f][1] = __float_as_uint(As[buf][base + 8 * ASTRIDE]);
                af[f][2] = __float_as_uint(As[buf][base + 4]);
                af[f][3] = __float_as_uint(As[buf][base + 8 * ASTRIDE + 4]);
            }
            #pragma unroll
            for (int f = 0; f < 4; f++)
                #pragma unroll
                for (int n = 0; n < 4; n++) {
                    unsigned bf[2] = { __float_as_uint(bcur[n].x), __float_as_uint(bcur[n].y) };
                    mma_tf32(c[f][n], af[f], bf);
                }
            #pragma unroll
            for (int n = 0; n < 4; n++) { bcur[n] = bn1[n]; bn1[n] = bn2[n]; }
        }
        if (!hasNext) break;
        asm volatile("cp.async.wait_group 0;" ::: "memory");
        __syncthreads();
        buf ^= 1;
    }

    #pragma unroll
    for (int f = 0; f < 4; f++) {
        int r0 = rowBase + wm * 64 + f * 16 + (lane >> 2);
        #pragma unroll
        for (int n = 0; n < 4; n++) {
            int cb = wn * 32 + n * 8 + (lane & 3) * 2;
            float b0 = bias[colInMat + cb], b1 = bias[colInMat + cb + 1];
            float v0 = c[f][n][0] + b0, v1 = c[f][n][1] + b1;
            float v2 = c[f][n][2] + b0, v3 = c[f][n][3] + b1;
            if (ACT == 1) {
                v0 = fmaxf(v0, 0.f); v1 = fmaxf(v1, 0.f);
                v2 = fmaxf(v2, 0.f); v3 = fmaxf(v3, 0.f);
            }
            *(float2*)&C[(size_t)r0 * ldc + colC + cb] = make_float2(v0, v1);
            *(float2*)&C[(size_t)(r0 + 8) * ldc + colC + cb] = make_float2(v2, v3);
        }
    }
}

// ---------------- qe: per-node projected query for edge scores ----------------
__global__ void qe_kernel(const float* __restrict__ We) {
    __shared__ float sWe[ED * D];
    __shared__ float sq[4][D];
    int tid = threadIdx.x;  // 256
    for (int i = tid; i < ED * D; i += 256) sWe[i] = We[i];
    int nodeBase = blockIdx.x * 4;
    for (int i = tid; i < 4 * D; i += 256) {
        int nn = i >> 7, c = i & 127;
        sq[nn][c] = g_qkvs[(size_t)(nodeBase + nn) * 512 + c];
    }
    __syncthreads();
    int nn = tid >> 6;
    int hf = tid & 63;
    int h = hf >> 4, f = hf & 15;
    float acc = 0.f;
    #pragma unroll
    for (int c = 0; c < 32; c++)
        acc += sq[nn][h * 32 + c] * sWe[f * D + h * 32 + c];
    g_qe[(size_t)(nodeBase + nn) * 64 + hf] = acc * 0.17677669529663687f;
}

// ---------------- fused attention: warp per (node, head), online softmax ----------------
// unrolled-by-2 edge loop: two independent shuffle-reduction chains in flight.
__global__ void __launch_bounds__(512, 2)
attn_kernel(const float* __restrict__ ea,
            const float* __restrict__ We, const float* __restrict__ be) {
    __shared__ float sWe[ED * D];
    __shared__ float sbe[D];
    int tid = threadIdx.x;  // 512 = 4 nodes x 4 heads
    for (int i = tid; i < ED * D; i += 512) sWe[i] = We[i];
    if (tid < D) sbe[tid] = be[tid];
    __syncthreads();
    int warp = tid >> 5, lane = tid & 31;
    int node = blockIdx.x * 4 + (warp >> 2);
    int h = warp & 3;
    int ch = (h << 5) | lane;
    float q = g_qkvs[(size_t)node * 512 + ch] * 0.17677669529663687f;
    float qe = (lane < 16) ? g_qe[(size_t)node * 64 + h * 16 + lane] : 0.f;
    int e0 = g_rowptr[node], e1 = g_rowptr[node + 1];
    float m = -INFINITY, den = 0.f, accv = 0.f, wea = 0.f;
    int e = e0;
    for (; e + 1 < e1; e += 2) {
        int s0 = g_csr_src[e],     id0 = g_csr_eid[e];
        int s1 = g_csr_src[e + 1], id1 = g_csr_eid[e + 1];
        const float* r0 = g_qkvs + (size_t)s0 * 512;
        const float* r1 = g_qkvs + (size_t)s1 * 512;
        float kk0 = r0[D + ch];
        float kk1 = r1[D + ch];
        float vv0 = r0[2 * D + ch];
        float vv1 = r1[2 * D + ch];
        float ea0 = (lane < 16) ? ea[(size_t)id0 * ED + lane] : 0.f;
        float ea1 = (lane < 16) ? ea[(size_t)id1 * ED + lane] : 0.f;
        float p0 = q * kk0 + qe * ea0;
        float p1 = q * kk1 + qe * ea1;
        #pragma unroll
        for (int o = 16; o; o >>= 1) {
            p0 += __shfl_xor_sync(0xffffffffu, p0, o);
            p1 += __shfl_xor_sync(0xffffffffu, p1, o);
        }
        float mn = fmaxf(m, fmaxf(p0, p1));
        float sc = __expf(m - mn);
        float w0 = __expf(p0 - mn);
        float w1 = __expf(p1 - mn);
        den  = den  * sc + w0 + w1;
        accv = accv * sc + w0 * vv0 + w1 * vv1;
        wea  = wea  * sc + w0 * ea0 + w1 * ea1;
        m = mn;
    }
    if (e < e1) {
        int s0 = g_csr_src[e], id0 = g_csr_eid[e];
        const float* r0 = g_qkvs + (size_t)s0 * 512;
        float kk0 = r0[D + ch];
        float vv0 = r0[2 * D + ch];
        float ea0 = (lane < 16) ? ea[(size_t)id0 * ED + lane] : 0.f;
        float p0 = q * kk0 + qe * ea0;
        #pragma unroll
        for (int o = 16; o; o >>= 1) p0 += __shfl_xor_sync(0xffffffffu, p0, o);
        float mn = fmaxf(m, p0);
        float sc = __expf(m - mn);
        float w0 = __expf(p0 - mn);
        den  = den  * sc + w0;
        accv = accv * sc + w0 * vv0;
        wea  = wea  * sc + w0 * ea0;
        m = mn;
    }
    float out = 0.f;
    if (e1 > e0) {
        float inv = 1.f / den;
        float wn = wea * inv;
        out = accv * inv + sbe[ch];
        #pragma unroll
        for (int f = 0; f < 16; f++) {
            float wf = __shfl_sync(0xffffffffu, wn, f);
            out += wf * sWe[f * D + ch];
        }
    }
    g_att[(size_t)node * D + ch] = out;
}

// ---------------- beta-gated skip + residual + LN1 (warp per node) ----------------
__global__ void betaln1_kernel(const float* __restrict__ Wb,
                               const float* __restrict__ g1, const float* __restrict__ b1) {
    int warp = threadIdx.x >> 5;
    int n = blockIdx.x * 8 + warp;
    int lane = threadIdx.x & 31;
    float o[4], xr[4];
    float bdot = 0.f;
    #pragma unroll
    for (int i = 0; i < 4; i++) {
        int c = lane + 32 * i;
        o[i] = g_att[(size_t)n * D + c];
        xr[i] = g_qkvs[(size_t)n * 512 + 384 + c];
        bdot += o[i] * Wb[c] + xr[i] * Wb[D + c] + (o[i] - xr[i]) * Wb[2 * D + c];
    }
    #pragma unroll
    for (int off = 16; off; off >>= 1) bdot += __shfl_xor_sync(0xffffffffu, bdot, off);
    float beta = 1.f / (1.f + __expf(-bdot));
    float hn[4];
    float s = 0.f;
    #pragma unroll
    for (int i = 0; i < 4; i++) {
        int c = lane + 32 * i;
        hn[i] = g_h[(size_t)n * D + c] + beta * xr[i] + (1.f - beta) * o[i];
        s += hn[i];
    }
    #pragma unroll
    for (int off = 16; off; off >>= 1) s += __shfl_xor_sync(0xffffffffu, s, off);
    float mean = s * (1.f / D);
    float vs = 0.f;
    #pragma unroll
    for (int i = 0; i < 4; i++) { float dd = hn[i] - mean; vs += dd * dd; }
    #pragma unroll
    for (int off = 16; off; off >>= 1) vs += __shfl_xor_sync(0xffffffffu, vs, off);
    float inv = rsqrtf(vs * (1.f / D) + 1e-5f);
    #pragma unroll
    for (int i = 0; i < 4; i++) {
        int c = lane + 32 * i;
        g_h[(size_t)n * D + c] = (hn[i] - mean) * inv * g1[c] + b1[c];
    }
}

// ---------------- residual + LN2 (warp per node) ----------------
__global__ void ln2_kernel(const float* __restrict__ g2, const float* __restrict__ b2) {
    int warp = threadIdx.x >> 5;
    int n = blockIdx.x * 8 + warp;
    int lane = threadIdx.x & 31;
    float hn[4];
    float s = 0.f;
    #pragma unroll
    for (int i = 0; i < 4; i++) {
        int c = lane + 32 * i;
        hn[i] = g_h[(size_t)n * D + c] + g_y[(size_t)n * D + c];
        s += hn[i];
    }
    #pragma unroll
    for (int off = 16; off; off >>= 1) s += __shfl_xor_sync(0xffffffffu, s, off);
    float mean = s * (1.f / D);
    float vs = 0.f;
    #pragma unroll
    for (int i = 0; i < 4; i++) { float dd = hn[i] - mean; vs += dd * dd; }
    #pragma unroll
    for (int off = 16; off; off >>= 1) vs += __shfl_xor_sync(0xffffffffu, vs, off);
    float inv = rsqrtf(vs * (1.f / D) + 1e-5f);
    #pragma unroll
    for (int i = 0; i < 4; i++) {
        int c = lane + 32 * i;
        g_h[(size_t)n * D + c] = (hn[i] - mean) * inv * g2[c] + b2[c];
    }
}

// ---------------- readout ----------------
__global__ void tmax_kernel(const int* __restrict__ t, const int* __restrict__ batch) {
    int n = blockIdx.x * blockDim.x + threadIdx.x;
    if (n < N_NODES) atomicMax(&g_tmax[batch[n]], t[n]);
}

__global__ void maskacc_kernel(const int* __restrict__ t, const int* __restrict__ batch) {
    int idx = blockIdx.x * blockDim.x + threadIdx.x;
    if (idx >= N_NODES * D) return;
    int n = idx >> 7, c = idx & 127;
    int b = batch[n];
    if (t[n] == g_tmax[b]) {
        float hv = g_h[idx];
        atomicAdd(&g_gsum[b * D + c], hv);
        atomicMax(&g_gmaxe[b * D + c], fenc(hv));
        if (c == 0) atomicAdd(&g_cnt[b], 1);
    }
}

__global__ void mlp_kernel(const float* __restrict__ Wh1, const float* __restrict__ bh1,
                           const float* __restrict__ Wh2, const float* __restrict__ bh2,
                           float* __restrict__ out) {
    __shared__ float sg[2 * D];
    __shared__ float sa[D];
    int g = blockIdx.x;
    int c = threadIdx.x;  // 128
    float cnt = fmaxf((float)g_cnt[g], 1.f);
    sg[c] = g_gsum[g * D + c] / cnt;
    sg[D + c] = fdec(g_gmaxe[g * D + c]);
    __syncthreads();
    float a = bh1[c];
    #pragma unroll 8
    for (int j = 0; j < 2 * D; j++) a += sg[j] * Wh1[j * D + c];
    sa[c] = fmaxf(a, 0.f);
    __syncthreads();
    if (c < 2) {
        float s2 = bh2[c];
        for (int j = 0; j < D; j++) s2 += sa[j] * Wh2[j * 2 + c];
        out[g * 2 + c] = s2;
    }
}

// ---------------- host orchestration ----------------
extern "C" void kernel_launch(void* const* d_in, const int* in_sizes, int n_in,
                              void* d_out, int out_size) {
    const float* x     = (const float*)d_in[0];
    const int*   t     = (const int*)d_in[1];
    const int*   ei    = (const int*)d_in[2];
    const float* ea    = (const float*)d_in[3];
    const int*   batch = (const int*)d_in[4];
    const float* Win   = (const float*)d_in[5];
    const float* b_in  = (const float*)d_in[6];
    const float* Wq    = (const float*)d_in[7];
    const float* bq    = (const float*)d_in[8];
    const float* Wk    = (const float*)d_in[9];
    const float* bk    = (const float*)d_in[10];
    const float* Wv    = (const float*)d_in[11];
    const float* bv    = (const float*)d_in[12];
    const float* We    = (const float*)d_in[13];
    const float* be    = (const float*)d_in[14];
    const float* Wskip = (const float*)d_in[15];
    const float* bskip = (const float*)d_in[16];
    const float* Wbeta = (const float*)d_in[17];
    const float* ln1_g = (const float*)d_in[18];
    const float* ln1_b = (const float*)d_in[19];
    const float* Wff1  = (const float*)d_in[20];
    const float* bff1  = (const float*)d_in[21];
    const float* Wff2  = (const float*)d_in[22];
    const float* bff2  = (const float*)d_in[23];
    const float* ln2_g = (const float*)d_in[24];
    const float* ln2_b = (const float*)d_in[25];
    const float* Wh1   = (const float*)d_in[26];
    const float* bh1   = (const float*)d_in[27];
    const float* Wh2   = (const float*)d_in[28];
    const float* bh2   = (const float*)d_in[29];
    float* out = (float*)d_out;

    float *p_h, *p_xt, *p_qkvs, *p_ff1, *p_y, *p_Wp, *p_Wp_in;
    cudaGetSymbolAddress((void**)&p_h, g_h);
    cudaGetSymbolAddress((void**)&p_xt, g_xt);
    cudaGetSymbolAddress((void**)&p_qkvs, g_qkvs);
    cudaGetSymbolAddress((void**)&p_ff1, g_ff1);
    cudaGetSymbolAddress((void**)&p_y, g_y);
    cudaGetSymbolAddress((void**)&p_Wp, g_Wp);
    cudaGetSymbolAddress((void**)&p_Wp_in, g_Wp_in);

    // order keeps the input tgemm at launch index 3 (ncu capture slot)
    prep_kernel<<<125, 256>>>();                                           // 0
    permute_kernel<<<dim3(48, 1), 256>>>(Win, p_Wp_in, XTDIM, D, 0, 0);    // 1
    build_xt_kernel<<<(N_NODES * XTDIM + 255) / 256, 256>>>(x, t);         // 2
    tgemm<1><<<dim3(1, 250), 256>>>(p_xt, p_Wp_in,                          // 3
                                    b_in, b_in, b_in, b_in,
                                    p_h, XTDIM, 1, D);
    deg_kernel<<<1000, 256>>>(ei);
    scanA_kernel<<<SCAN_BLOCKS, 256>>>();
    scanB_kernel<<<1, 128>>>();
    scanC_kernel<<<SCAN_BLOCKS, 256>>>();
    fill_kernel<<<1000, 256>>>(ei);
    permute_kernel<<<dim3(64, LAYERS), 256>>>(Wq,    p_Wp + 0 * 16384,  D, D,   D * D,    WP_LAYER);
    permute_kernel<<<dim3(64, LAYERS), 256>>>(Wk,    p_Wp + 1 * 16384,  D, D,   D * D,    WP_LAYER);
    permute_kernel<<<dim3(64, LAYERS), 256>>>(Wv,    p_Wp + 2 * 16384,  D, D,   D * D,    WP_LAYER);
    permute_kernel<<<dim3(64, LAYERS), 256>>>(Wskip, p_Wp + 3 * 16384,  D, D,   D * D,    WP_LAYER);
    permute_kernel<<<dim3(256, LAYERS), 256>>>(Wff1, p_Wp + WP_FF1_OFF, D, FFD, D * FFD,  WP_LAYER);
    permute_kernel<<<dim3(256, LAYERS), 256>>>(Wff2, p_Wp + WP_FF2_OFF, FFD, D, FFD * D,  WP_LAYER);

    for (int i = 0; i < LAYERS; i++) {
        const float* Wei = We + (size_t)i * ED * D;
        float* WpL = p_Wp + (size_t)i * WP_LAYER;
        tgemm<0><<<dim3(4, 250), 256>>>(p_h, WpL,
                                        bq + i * D, bk + i * D, bv + i * D, bskip + i * D,
                                        p_qkvs, D, 1, 512);
        qe_kernel<<<N_NODES / 4, 256>>>(Wei);
        attn_kernel<<<N_NODES / 4, 512>>>(ea, Wei, be + i * D);
        betaln1_kernel<<<N_NODES / 8, 256>>>(Wbeta + (size_t)i * 3 * D, ln1_g + i * D, ln1_b + i * D);

        tgemm<1><<<dim3(4, 250), 256>>>(p_h, WpL + WP_FF1_OFF,
                                        bff1 + i * FFD, nullptr, nullptr, nullptr,
                                        p_ff1, D, 4, FFD);
        tgemm<0><<<dim3(1, 250), 256>>>(p_ff1, WpL + WP_FF2_OFF,
                                        bff2 + i * D, nullptr, nullptr, nullptr,
                                        p_y, FFD, 1, D);
        ln2_kernel<<<N_NODES / 8, 256>>>(ln2_g + i * D, ln2_b + i * D);
    }

    tmax_kernel<<<125, 256>>>(t, batch);
    maskacc_kernel<<<(N_NODES * D + 255) / 256, 256>>>(t, batch);
    mlp_kernel<<<N_GRAPHS, 128>>>(Wh1, bh1, Wh2, bh2, out);
    (void)in_sizes; (void)n_in; (void)out_size;
}